// round 3
// baseline (speedup 1.0000x reference)
#include <cuda_runtime.h>
#include <math.h>

#define BSZ 2048
#define INSZ 256
#define CSZ 256
#define MSZ 1024
#define DSZ 32
#define OUTSZ 256

// ---------------- scratch (static device globals; no allocation) ----------------
__device__ float g_gates[BSZ * 4 * CSZ];   // 8 MB
__device__ float g_logits[BSZ * MSZ];      // 8 MB (becomes w_w in-place after softmax)
__device__ float g_h[BSZ * CSZ];           // 2 MB
__device__ float g_e[BSZ * DSZ];
__device__ float g_a[BSZ * DSZ];
__device__ float g_rvec[DSZ];
__device__ float g_g0[4 * CSZ];
__device__ float g_outr[OUTSZ];

// ---------------- kernel 1: read head (batch-independent since h=0) ----------------
// w_r = softmax(b_rattn); rvec = w_r @ memory
__global__ __launch_bounds__(256) void k_read(const float* __restrict__ b_rattn,
                                              const float* __restrict__ memory) {
    __shared__ float p[MSZ];
    __shared__ float red[256];
    int tid = threadIdx.x;
    float v[4];
    float lm = -1e30f;
#pragma unroll
    for (int i = 0; i < 4; i++) {
        v[i] = b_rattn[tid + i * 256];
        lm = fmaxf(lm, v[i]);
    }
    red[tid] = lm;
    __syncthreads();
    for (int s = 128; s > 0; s >>= 1) {
        if (tid < s) red[tid] = fmaxf(red[tid], red[tid + s]);
        __syncthreads();
    }
    float mx = red[0];
    __syncthreads();
    float ls = 0.f;
#pragma unroll
    for (int i = 0; i < 4; i++) {
        float e = expf(v[i] - mx);
        p[tid + i * 256] = e;
        ls += e;
    }
    red[tid] = ls;
    __syncthreads();
    for (int s = 128; s > 0; s >>= 1) {
        if (tid < s) red[tid] += red[tid + s];
        __syncthreads();
    }
    float inv = 1.f / red[0];
    __syncthreads();
    // rvec: tid -> d = tid%32, chunk = tid/32 over 128 m each
    int d = tid & 31, ch = tid >> 5;
    float s = 0.f;
    int m0 = ch * 128;
    for (int m = m0; m < m0 + 128; m++) s += p[m] * memory[m * DSZ + d];
    red[tid] = s * inv;
    __syncthreads();
    if (tid < 32) {
        float t = 0.f;
#pragma unroll
        for (int c = 0; c < 8; c++) t += red[c * 32 + tid];
        g_rvec[tid] = t;
    }
}

// ---------------- kernel 2: fold rvec into gate bias g0 and output bias outr ----------------
__global__ __launch_bounds__(256) void k_prep(const float* __restrict__ W_ih,
                                              const float* __restrict__ b_ih,
                                              const float* __restrict__ b_hh,
                                              const float* __restrict__ W_out,
                                              const float* __restrict__ b_out) {
    __shared__ float rv[DSZ];
    if (threadIdx.x < DSZ) rv[threadIdx.x] = g_rvec[threadIdx.x];
    __syncthreads();
    int idx = blockIdx.x * 256 + threadIdx.x;
    if (idx < 4 * CSZ) {
        const float* w = W_ih + (size_t)idx * (INSZ + DSZ) + INSZ;
        float s = b_ih[idx] + b_hh[idx];
#pragma unroll
        for (int d = 0; d < DSZ; d++) s += w[d] * rv[d];
        g_g0[idx] = s;
    } else if (idx < 4 * CSZ + OUTSZ) {
        int o = idx - 4 * CSZ;
        const float* w = W_out + (size_t)o * (CSZ + DSZ) + CSZ;
        float s = b_out[o];
#pragma unroll
        for (int d = 0; d < DSZ; d++) s += w[d] * rv[d];
        g_outr[o] = s;
    }
}

// ---------------- tiled SGEMM: C[b,n] = sum_k A[b,k] * W[n*ldw + k] + bias[n] ----------------
// K = 256 fixed, lda = 256 fixed. BM=BN=128, BK=16, 256 threads, 8x8 microtile.
// bias_mode: 0 -> g_g0, 1 -> bias_ext, 2 -> g_outr
__global__ __launch_bounds__(256) void sgemm_bias(const float* __restrict__ A,
                                                  const float* __restrict__ W, int ldw,
                                                  const float* __restrict__ bias_ext,
                                                  int bias_mode,
                                                  float* __restrict__ C, int N) {
    __shared__ float As[16][128];
    __shared__ float Ws[16][128];
    const int tid = threadIdx.x;
    const int bm = blockIdx.y, bn = blockIdx.x;
    const int lrow = tid >> 2;       // 0..63
    const int lk = (tid & 3) << 2;   // 0,4,8,12
    const int ty = tid >> 4, tx = tid & 15;

    float acc[8][8];
#pragma unroll
    for (int i = 0; i < 8; i++)
#pragma unroll
        for (int j = 0; j < 8; j++) acc[i][j] = 0.f;

    const float* Ap = A + (size_t)(bm * 128) * 256;
    const float* Wp = W + (size_t)(bn * 128) * ldw;

    for (int k0 = 0; k0 < 256; k0 += 16) {
#pragma unroll
        for (int r = 0; r < 2; r++) {
            int row = lrow + r * 64;
            float4 va = *(const float4*)(Ap + (size_t)row * 256 + k0 + lk);
            As[lk + 0][row] = va.x; As[lk + 1][row] = va.y;
            As[lk + 2][row] = va.z; As[lk + 3][row] = va.w;
            float4 vw = *(const float4*)(Wp + (size_t)row * ldw + k0 + lk);
            Ws[lk + 0][row] = vw.x; Ws[lk + 1][row] = vw.y;
            Ws[lk + 2][row] = vw.z; Ws[lk + 3][row] = vw.w;
        }
        __syncthreads();
#pragma unroll
        for (int kk = 0; kk < 16; kk++) {
            float4 a0 = *(const float4*)&As[kk][ty * 8];
            float4 a1 = *(const float4*)&As[kk][ty * 8 + 4];
            float4 b0 = *(const float4*)&Ws[kk][tx * 8];
            float4 b1 = *(const float4*)&Ws[kk][tx * 8 + 4];
            float ra[8] = {a0.x, a0.y, a0.z, a0.w, a1.x, a1.y, a1.z, a1.w};
            float rb[8] = {b0.x, b0.y, b0.z, b0.w, b1.x, b1.y, b1.z, b1.w};
#pragma unroll
            for (int i = 0; i < 8; i++)
#pragma unroll
                for (int j = 0; j < 8; j++) acc[i][j] += ra[i] * rb[j];
        }
        __syncthreads();
    }

    const float* bias = (bias_mode == 0) ? g_g0 : (bias_mode == 2 ? g_outr : bias_ext);
    float bj[8];
#pragma unroll
    for (int j = 0; j < 8; j++) bj[j] = bias[bn * 128 + tx * 8 + j];
#pragma unroll
    for (int i = 0; i < 8; i++) {
        int row = bm * 128 + ty * 8 + i;
        float* cp = C + (size_t)row * N + bn * 128 + tx * 8;
#pragma unroll
        for (int j = 0; j < 8; j++) cp[j] = acc[i][j] + bj[j];
    }
}

// ---------------- kernel 4: LSTM activations (c=0 -> c_new = i*g; h = o*tanh(c_new)) ----------------
__global__ __launch_bounds__(256) void k_lstm() {
    int idx = blockIdx.x * 256 + threadIdx.x;  // < 2048*256
    int b = idx >> 8;
    int j = idx & 255;
    const float* g = g_gates + (size_t)b * (4 * CSZ);
    float ig = 1.f / (1.f + expf(-g[j]));
    float gg = tanhf(g[2 * CSZ + j]);
    float og = 1.f / (1.f + expf(-g[3 * CSZ + j]));
    g_h[idx] = og * tanhf(ig * gg);
}

// ---------------- kernel 5: erase/add vectors (small GEMV per row) ----------------
__global__ __launch_bounds__(64) void k_erad(const float* __restrict__ W_er,
                                             const float* __restrict__ b_er,
                                             const float* __restrict__ W_ad,
                                             const float* __restrict__ b_ad) {
    int b = blockIdx.x;
    __shared__ float h[CSZ];
    int tid = threadIdx.x;
    for (int i = tid; i < CSZ; i += 64) h[i] = g_h[(size_t)b * CSZ + i];
    __syncthreads();
    if (tid < 32) {
        const float4* w = (const float4*)(W_er + (size_t)tid * CSZ);
        const float4* hv = (const float4*)h;
        float s = b_er[tid];
#pragma unroll
        for (int k = 0; k < 64; k++) {
            float4 a = w[k], x = hv[k];
            s += a.x * x.x + a.y * x.y + a.z * x.z + a.w * x.w;
        }
        g_e[b * DSZ + tid] = 1.f / (1.f + expf(-s));
    } else {
        int t = tid - 32;
        const float4* w = (const float4*)(W_ad + (size_t)t * CSZ);
        const float4* hv = (const float4*)h;
        float s = b_ad[t];
#pragma unroll
        for (int k = 0; k < 64; k++) {
            float4 a = w[k], x = hv[k];
            s += a.x * x.x + a.y * x.y + a.z * x.z + a.w * x.w;
        }
        g_a[b * DSZ + t] = tanhf(s);
    }
}

// ---------------- kernel 6: row softmax over wattn logits (in-place -> w_w) ----------------
__global__ __launch_bounds__(256) void k_softmax() {
    float4* row = (float4*)(g_logits + (size_t)blockIdx.x * MSZ);
    int tid = threadIdx.x;
    __shared__ float red[256];
    float4 v = row[tid];
    float lm = fmaxf(fmaxf(v.x, v.y), fmaxf(v.z, v.w));
    red[tid] = lm;
    __syncthreads();
    for (int s = 128; s > 0; s >>= 1) {
        if (tid < s) red[tid] = fmaxf(red[tid], red[tid + s]);
        __syncthreads();
    }
    float mx = red[0];
    __syncthreads();
    v.x = expf(v.x - mx); v.y = expf(v.y - mx);
    v.z = expf(v.z - mx); v.w = expf(v.w - mx);
    red[tid] = v.x + v.y + v.z + v.w;
    __syncthreads();
    for (int s = 128; s > 0; s >>= 1) {
        if (tid < s) red[tid] += red[tid + s];
        __syncthreads();
    }
    float inv = 1.f / red[0];
    v.x *= inv; v.y *= inv; v.z *= inv; v.w *= inv;
    row[tid] = v;
}

// ---------------- kernel 7: write_data (HBM-store-bound) ----------------
// out[b,m,d] = memory[m,d]*(1 - w_w[b,m]*e[b,d]) + w_w[b,m]*a[b,d]
// block: 32 m-rows x 8 batch rows; thread = one float4 of the memory tile.
__global__ __launch_bounds__(256) void k_write(const float* __restrict__ memory,
                                               float* __restrict__ outw) {
    __shared__ float4 memS[256];     // [m_local(32)][d4(8)]
    __shared__ float wS[8][32];
    __shared__ float4 eS[8][8];
    __shared__ float4 aS[8][8];
    int tid = threadIdx.x;
    int m0 = blockIdx.x * 32;
    int b0 = blockIdx.y * 8;

    memS[tid] = ((const float4*)memory)[(size_t)(m0 + (tid >> 3)) * 8 + (tid & 7)];
    {
        int bi = tid >> 5, ml = tid & 31;
        wS[bi][ml] = g_logits[(size_t)(b0 + bi) * MSZ + m0 + ml];
    }
    if (tid < 64) {
        eS[tid >> 3][tid & 7] = ((const float4*)g_e)[(size_t)(b0 + (tid >> 3)) * 8 + (tid & 7)];
    } else if (tid < 128) {
        int t = tid - 64;
        aS[t >> 3][t & 7] = ((const float4*)g_a)[(size_t)(b0 + (t >> 3)) * 8 + (t & 7)];
    }
    __syncthreads();

    int ml = tid >> 3, d4 = tid & 7;
    float4 mv = memS[tid];
#pragma unroll
    for (int bi = 0; bi < 8; bi++) {
        float w = wS[bi][ml];
        float4 e = eS[bi][d4];
        float4 a = aS[bi][d4];
        float4 r;
        r.x = mv.x * (1.f - w * e.x) + w * a.x;
        r.y = mv.y * (1.f - w * e.y) + w * a.y;
        r.z = mv.z * (1.f - w * e.z) + w * a.z;
        r.w = mv.w * (1.f - w * e.w) + w * a.w;
        ((float4*)outw)[((size_t)(b0 + bi) * MSZ + m0 + ml) * 8 + d4] = r;
    }
}

// ---------------- launch ----------------
extern "C" void kernel_launch(void* const* d_in, const int* in_sizes, int n_in,
                              void* d_out, int out_size) {
    const float* x       = (const float*)d_in[0];
    const float* memory  = (const float*)d_in[1];
    // d_in[2] = W_rattn (dead: h=0), d_in[5] = W_hh (dead: h=0)
    const float* b_rattn = (const float*)d_in[3];
    const float* W_ih    = (const float*)d_in[4];
    const float* b_ih    = (const float*)d_in[6];
    const float* b_hh    = (const float*)d_in[7];
    const float* W_wattn = (const float*)d_in[8];
    const float* b_wattn = (const float*)d_in[9];
    const float* W_er    = (const float*)d_in[10];
    const float* b_er    = (const float*)d_in[11];
    const float* W_ad    = (const float*)d_in[12];
    const float* b_ad    = (const float*)d_in[13];
    const float* W_out   = (const float*)d_in[14];
    // b_out folded into g_outr via k_prep
    const float* b_out   = (const float*)d_in[15];

    float* out = (float*)d_out;            // [2048, 256]
    float* outw = out + BSZ * OUTSZ;       // [2048, 1024, 32]

    float *p_gates, *p_logits, *p_h;
    cudaGetSymbolAddress((void**)&p_gates, g_gates);
    cudaGetSymbolAddress((void**)&p_logits, g_logits);
    cudaGetSymbolAddress((void**)&p_h, g_h);

    k_read<<<1, 256>>>(b_rattn, memory);
    k_prep<<<5, 256>>>(W_ih, b_ih, b_hh, W_out, b_out);

    // gates = x @ W_ih[:, :256]^T + g0
    sgemm_bias<<<dim3(8, 16), 256>>>(x, W_ih, INSZ + DSZ, nullptr, 0, p_gates, 4 * CSZ);
    k_lstm<<<BSZ, 256>>>();

    // wattn logits = h @ W_wattn^T + b_wattn
    sgemm_bias<<<dim3(8, 16), 256>>>(p_h, W_wattn, CSZ, b_wattn, 1, p_logits, MSZ);
    // output = h @ W_out[:, :256]^T + outr  (rvec part folded into outr)
    sgemm_bias<<<dim3(2, 16), 256>>>(p_h, W_out, CSZ + DSZ, nullptr, 2, out, OUTSZ);

    k_erad<<<BSZ, 64>>>(W_er, b_er, W_ad, b_ad);
    k_softmax<<<BSZ, 256>>>();
    k_write<<<dim3(MSZ / 32, BSZ / 8), 256>>>(memory, outw);
}

// round 9
// speedup vs baseline: 1.6398x; 1.6398x over previous
#include <cuda_runtime.h>
#include <math.h>

#define BSZ 2048
#define INSZ 256
#define CSZ 256
#define MSZ 1024
#define DSZ 32
#define OUTSZ 256

// ---------------- scratch (static device globals; no allocation) ----------------
__device__ float g_logits[BSZ * MSZ];      // 8 MB (becomes w_w in-place after softmax)
__device__ float g_h[BSZ * CSZ];           // 2 MB
__device__ float g_e[BSZ * DSZ];
__device__ float g_a[BSZ * DSZ];
__device__ float g_rvec[DSZ];
__device__ float g_g0[4 * CSZ];
__device__ float g_outr[OUTSZ];

// ---------------- tf32 helpers ----------------
__device__ __forceinline__ unsigned f2tf32(float x) {
    unsigned r;
    asm("cvt.rna.tf32.f32 %0, %1;" : "=r"(r) : "f"(x));
    return r;
}

__device__ __forceinline__ void mma8(float* d, const unsigned* a, const unsigned* b) {
    asm volatile(
        "mma.sync.aligned.m16n8k8.row.col.f32.tf32.tf32.f32 "
        "{%0,%1,%2,%3}, {%4,%5,%6,%7}, {%8,%9}, {%0,%1,%2,%3};"
        : "+f"(d[0]), "+f"(d[1]), "+f"(d[2]), "+f"(d[3])
        : "r"(a[0]), "r"(a[1]), "r"(a[2]), "r"(a[3]), "r"(b[0]), "r"(b[1]));
}

__device__ __forceinline__ float sigf(float x) { return 1.f / (1.f + expf(-x)); }

// ---------------- kernel 1: read head (batch-independent since h=0) ----------------
__global__ __launch_bounds__(256) void k_read(const float* __restrict__ b_rattn,
                                              const float* __restrict__ memory) {
    __shared__ float p[MSZ];
    __shared__ float red[256];
    int tid = threadIdx.x;
    float v[4];
    float lm = -1e30f;
#pragma unroll
    for (int i = 0; i < 4; i++) {
        v[i] = b_rattn[tid + i * 256];
        lm = fmaxf(lm, v[i]);
    }
    red[tid] = lm;
    __syncthreads();
    for (int s = 128; s > 0; s >>= 1) {
        if (tid < s) red[tid] = fmaxf(red[tid], red[tid + s]);
        __syncthreads();
    }
    float mx = red[0];
    __syncthreads();
    float ls = 0.f;
#pragma unroll
    for (int i = 0; i < 4; i++) {
        float e = expf(v[i] - mx);
        p[tid + i * 256] = e;
        ls += e;
    }
    red[tid] = ls;
    __syncthreads();
    for (int s = 128; s > 0; s >>= 1) {
        if (tid < s) red[tid] += red[tid + s];
        __syncthreads();
    }
    float inv = 1.f / red[0];
    __syncthreads();
    int d = tid & 31, ch = tid >> 5;
    float s = 0.f;
    int m0 = ch * 128;
    for (int m = m0; m < m0 + 128; m++) s += p[m] * memory[m * DSZ + d];
    red[tid] = s * inv;
    __syncthreads();
    if (tid < 32) {
        float t = 0.f;
#pragma unroll
        for (int c = 0; c < 8; c++) t += red[c * 32 + tid];
        g_rvec[tid] = t;
    }
}

// ---------------- kernel 2: fold rvec into gate bias g0 and output bias outr ----------------
__global__ __launch_bounds__(256) void k_prep(const float* __restrict__ W_ih,
                                              const float* __restrict__ b_ih,
                                              const float* __restrict__ b_hh,
                                              const float* __restrict__ W_out,
                                              const float* __restrict__ b_out) {
    __shared__ float rv[DSZ];
    if (threadIdx.x < DSZ) rv[threadIdx.x] = g_rvec[threadIdx.x];
    __syncthreads();
    int idx = blockIdx.x * 256 + threadIdx.x;
    if (idx < 4 * CSZ) {
        const float* w = W_ih + (size_t)idx * (INSZ + DSZ) + INSZ;
        float s = b_ih[idx] + b_hh[idx];
#pragma unroll
        for (int d = 0; d < DSZ; d++) s += w[d] * rv[d];
        g_g0[idx] = s;
    } else if (idx < 4 * CSZ + OUTSZ) {
        int o = idx - 4 * CSZ;
        const float* w = W_out + (size_t)o * (CSZ + DSZ) + CSZ;
        float s = b_out[o];
#pragma unroll
        for (int d = 0; d < DSZ; d++) s += w[d] * rv[d];
        g_outr[o] = s;
    }
}

// ---------------- kernel 3: fused gates GEMM (tf32) + LSTM epilogue -> h ----------------
// Computes i/g/o gate slices (f dead, c=0) for 64 batch rows x 64 j-cols per block,
// applies LSTM nonlinearity, writes h directly.
// block: 256 thr = 8 warps (2 m x 4 n), warp tile 32x16, mma m16n8k8.
__global__ __launch_bounds__(256, 1) void k_gates(const float* __restrict__ x,
                                                  const float* __restrict__ W_ih,
                                                  float* __restrict__ hout) {
    __shared__ unsigned As[64][36];
    __shared__ unsigned Ws[3][64][36];
    const int tid = threadIdx.x;
    const int wid = tid >> 5, lane = tid & 31;
    const int gid = lane >> 2, tig = lane & 3;
    const int warp_m = wid & 1, warp_n = wid >> 1;
    const int bm = blockIdx.y, jn = blockIdx.x;
    const int lrow = tid >> 3, lk4 = (tid & 7) << 2;
    const int gate_off[3] = {0, 2 * CSZ, 3 * CSZ};

    float acc[3][2][2][4];
#pragma unroll
    for (int g = 0; g < 3; g++)
#pragma unroll
        for (int mt = 0; mt < 2; mt++)
#pragma unroll
            for (int nt = 0; nt < 2; nt++)
#pragma unroll
                for (int e = 0; e < 4; e++) acc[g][mt][nt][e] = 0.f;

    const float* Ap = x + (size_t)(bm * 64) * INSZ;

    for (int k0 = 0; k0 < 256; k0 += 32) {
#pragma unroll
        for (int r = 0; r < 2; r++) {
            int row = lrow + 32 * r;
            float4 v = *(const float4*)(Ap + (size_t)row * INSZ + k0 + lk4);
            *(uint4*)&As[row][lk4] = make_uint4(f2tf32(v.x), f2tf32(v.y), f2tf32(v.z), f2tf32(v.w));
        }
#pragma unroll
        for (int g = 0; g < 3; g++)
#pragma unroll
            for (int r = 0; r < 2; r++) {
                int row = lrow + 32 * r;
                int wr = gate_off[g] + jn * 64 + row;
                float4 v = *(const float4*)(W_ih + (size_t)wr * (INSZ + DSZ) + k0 + lk4);
                *(uint4*)&Ws[g][row][lk4] = make_uint4(f2tf32(v.x), f2tf32(v.y), f2tf32(v.z), f2tf32(v.w));
            }
        __syncthreads();
#pragma unroll
        for (int kk = 0; kk < 4; kk++) {
            int kb = kk * 8;
            unsigned af[2][4];
#pragma unroll
            for (int mt = 0; mt < 2; mt++) {
                int r0 = warp_m * 32 + mt * 16 + gid;
                af[mt][0] = As[r0][kb + tig];
                af[mt][1] = As[r0 + 8][kb + tig];
                af[mt][2] = As[r0][kb + tig + 4];
                af[mt][3] = As[r0 + 8][kb + tig + 4];
            }
#pragma unroll
            for (int g = 0; g < 3; g++) {
                unsigned bf[2][2];
#pragma unroll
                for (int nt = 0; nt < 2; nt++) {
                    int n0 = warp_n * 16 + nt * 8 + gid;
                    bf[nt][0] = Ws[g][n0][kb + tig];
                    bf[nt][1] = Ws[g][n0][kb + tig + 4];
                }
#pragma unroll
                for (int mt = 0; mt < 2; mt++)
#pragma unroll
                    for (int nt = 0; nt < 2; nt++) mma8(acc[g][mt][nt], af[mt], bf[nt]);
            }
        }
        __syncthreads();
    }

    // LSTM epilogue: h = sigmoid(o) * tanh(sigmoid(i) * tanh(g))
#pragma unroll
    for (int mt = 0; mt < 2; mt++)
#pragma unroll
        for (int nt = 0; nt < 2; nt++) {
            int row = bm * 64 + warp_m * 32 + mt * 16 + gid;
            int col = jn * 64 + warp_n * 16 + nt * 8 + 2 * tig;
            float bi0 = g_g0[col], bi1 = g_g0[col + 1];
            float bg0 = g_g0[2 * CSZ + col], bg1 = g_g0[2 * CSZ + col + 1];
            float bo0 = g_g0[3 * CSZ + col], bo1 = g_g0[3 * CSZ + col + 1];
            float i0 = acc[0][mt][nt][0] + bi0, i1 = acc[0][mt][nt][1] + bi1;
            float i2 = acc[0][mt][nt][2] + bi0, i3 = acc[0][mt][nt][3] + bi1;
            float gg0 = acc[1][mt][nt][0] + bg0, gg1 = acc[1][mt][nt][1] + bg1;
            float gg2 = acc[1][mt][nt][2] + bg0, gg3 = acc[1][mt][nt][3] + bg1;
            float o0 = acc[2][mt][nt][0] + bo0, o1 = acc[2][mt][nt][1] + bo1;
            float o2 = acc[2][mt][nt][2] + bo0, o3 = acc[2][mt][nt][3] + bo1;
            hout[(size_t)row * CSZ + col]           = sigf(o0) * tanhf(sigf(i0) * tanhf(gg0));
            hout[(size_t)row * CSZ + col + 1]       = sigf(o1) * tanhf(sigf(i1) * tanhf(gg1));
            hout[(size_t)(row + 8) * CSZ + col]     = sigf(o2) * tanhf(sigf(i2) * tanhf(gg2));
            hout[(size_t)(row + 8) * CSZ + col + 1] = sigf(o3) * tanhf(sigf(i3) * tanhf(gg3));
        }
}

// ---------------- generic tf32 GEMM: C[m,n] = sum_k A[m,k]*W[n*ldw+k] + bias[n] ----------------
// 256 thr = 8 warps (2 m x 4 n). Warp tile (BM/2) x (BN/4). K = 256.
template <int BM, int BN>
__global__ __launch_bounds__(256, 1) void gemm_tf32(const float* __restrict__ A,
                                                    const float* __restrict__ W, int ldw,
                                                    const float* __restrict__ bias,
                                                    float* __restrict__ C, int N) {
    constexpr int MT = BM / 32;  // m16 tiles per warp
    constexpr int NT = BN / 32;  // n8 tiles per warp
    __shared__ unsigned As[BM][36];
    __shared__ unsigned Ws[BN][36];
    const int tid = threadIdx.x;
    const int wid = tid >> 5, lane = tid & 31;
    const int gid = lane >> 2, tig = lane & 3;
    const int warp_m = wid & 1, warp_n = wid >> 1;
    const int bm = blockIdx.y, bn = blockIdx.x;
    const int lrow = tid >> 3, lk4 = (tid & 7) << 2;

    float acc[MT][NT][4];
#pragma unroll
    for (int mt = 0; mt < MT; mt++)
#pragma unroll
        for (int nt = 0; nt < NT; nt++)
#pragma unroll
            for (int e = 0; e < 4; e++) acc[mt][nt][e] = 0.f;

    const float* Ap = A + (size_t)(bm * BM) * 256;
    const float* Wp = W + (size_t)(bn * BN) * ldw;

    for (int k0 = 0; k0 < 256; k0 += 32) {
#pragma unroll
        for (int r = 0; r < BM / 32; r++) {
            int row = lrow + 32 * r;
            float4 v = *(const float4*)(Ap + (size_t)row * 256 + k0 + lk4);
            *(uint4*)&As[row][lk4] = make_uint4(f2tf32(v.x), f2tf32(v.y), f2tf32(v.z), f2tf32(v.w));
        }
#pragma unroll
        for (int r = 0; r < BN / 32; r++) {
            int row = lrow + 32 * r;
            float4 v = *(const float4*)(Wp + (size_t)row * ldw + k0 + lk4);
            *(uint4*)&Ws[row][lk4] = make_uint4(f2tf32(v.x), f2tf32(v.y), f2tf32(v.z), f2tf32(v.w));
        }
        __syncthreads();
#pragma unroll
        for (int kk = 0; kk < 4; kk++) {
            int kb = kk * 8;
            unsigned af[MT][4];
#pragma unroll
            for (int mt = 0; mt < MT; mt++) {
                int r0 = warp_m * (BM / 2) + mt * 16 + gid;
                af[mt][0] = As[r0][kb + tig];
                af[mt][1] = As[r0 + 8][kb + tig];
                af[mt][2] = As[r0][kb + tig + 4];
                af[mt][3] = As[r0 + 8][kb + tig + 4];
            }
            unsigned bf[NT][2];
#pragma unroll
            for (int nt = 0; nt < NT; nt++) {
                int n0 = warp_n * (BN / 4) + nt * 8 + gid;
                bf[nt][0] = Ws[n0][kb + tig];
                bf[nt][1] = Ws[n0][kb + tig + 4];
            }
#pragma unroll
            for (int mt = 0; mt < MT; mt++)
#pragma unroll
                for (int nt = 0; nt < NT; nt++) mma8(acc[mt][nt], af[mt], bf[nt]);
        }
        __syncthreads();
    }

#pragma unroll
    for (int mt = 0; mt < MT; mt++)
#pragma unroll
        for (int nt = 0; nt < NT; nt++) {
            int row = bm * BM + warp_m * (BM / 2) + mt * 16 + gid;
            int col = bn * BN + warp_n * (BN / 4) + nt * 8 + 2 * tig;
            float b0 = bias[col], b1 = bias[col + 1];
            C[(size_t)row * N + col]           = acc[mt][nt][0] + b0;
            C[(size_t)row * N + col + 1]       = acc[mt][nt][1] + b1;
            C[(size_t)(row + 8) * N + col]     = acc[mt][nt][2] + b0;
            C[(size_t)(row + 8) * N + col + 1] = acc[mt][nt][3] + b1;
        }
}

// ---------------- kernel 5: erase/add vectors ----------------
__global__ __launch_bounds__(64) void k_erad(const float* __restrict__ W_er,
                                             const float* __restrict__ b_er,
                                             const float* __restrict__ W_ad,
                                             const float* __restrict__ b_ad) {
    int b = blockIdx.x;
    __shared__ float h[CSZ];
    int tid = threadIdx.x;
    for (int i = tid; i < CSZ; i += 64) h[i] = g_h[(size_t)b * CSZ + i];
    __syncthreads();
    if (tid < 32) {
        const float4* w = (const float4*)(W_er + (size_t)tid * CSZ);
        const float4* hv = (const float4*)h;
        float s = b_er[tid];
#pragma unroll
        for (int k = 0; k < 64; k++) {
            float4 a = w[k], xv = hv[k];
            s += a.x * xv.x + a.y * xv.y + a.z * xv.z + a.w * xv.w;
        }
        g_e[b * DSZ + tid] = 1.f / (1.f + expf(-s));
    } else {
        int t = tid - 32;
        const float4* w = (const float4*)(W_ad + (size_t)t * CSZ);
        const float4* hv = (const float4*)h;
        float s = b_ad[t];
#pragma unroll
        for (int k = 0; k < 64; k++) {
            float4 a = w[k], xv = hv[k];
            s += a.x * xv.x + a.y * xv.y + a.z * xv.z + a.w * xv.w;
        }
        g_a[b * DSZ + t] = tanhf(s);
    }
}

// ---------------- kernel 6: row softmax over wattn logits (in-place -> w_w) ----------------
__global__ __launch_bounds__(256) void k_softmax() {
    float4* row = (float4*)(g_logits + (size_t)blockIdx.x * MSZ);
    int tid = threadIdx.x;
    __shared__ float red[256];
    float4 v = row[tid];
    float lm = fmaxf(fmaxf(v.x, v.y), fmaxf(v.z, v.w));
    red[tid] = lm;
    __syncthreads();
    for (int s = 128; s > 0; s >>= 1) {
        if (tid < s) red[tid] = fmaxf(red[tid], red[tid + s]);
        __syncthreads();
    }
    float mx = red[0];
    __syncthreads();
    v.x = expf(v.x - mx); v.y = expf(v.y - mx);
    v.z = expf(v.z - mx); v.w = expf(v.w - mx);
    red[tid] = v.x + v.y + v.z + v.w;
    __syncthreads();
    for (int s = 128; s > 0; s >>= 1) {
        if (tid < s) red[tid] += red[tid + s];
        __syncthreads();
    }
    float inv = 1.f / red[0];
    v.x *= inv; v.y *= inv; v.z *= inv; v.w *= inv;
    row[tid] = v;
}

// ---------------- kernel 7: write_data (HBM-store-bound) ----------------
__global__ __launch_bounds__(256) void k_write(const float* __restrict__ memory,
                                               float* __restrict__ outw) {
    __shared__ float4 memS[256];
    __shared__ float wS[8][32];
    __shared__ float4 eS[8][8];
    __shared__ float4 aS[8][8];
    int tid = threadIdx.x;
    int m0 = blockIdx.x * 32;
    int b0 = blockIdx.y * 8;

    memS[tid] = ((const float4*)memory)[(size_t)(m0 + (tid >> 3)) * 8 + (tid & 7)];
    {
        int bi = tid >> 5, ml = tid & 31;
        wS[bi][ml] = g_logits[(size_t)(b0 + bi) * MSZ + m0 + ml];
    }
    if (tid < 64) {
        eS[tid >> 3][tid & 7] = ((const float4*)g_e)[(size_t)(b0 + (tid >> 3)) * 8 + (tid & 7)];
    } else if (tid < 128) {
        int t = tid - 64;
        aS[t >> 3][t & 7] = ((const float4*)g_a)[(size_t)(b0 + (t >> 3)) * 8 + (t & 7)];
    }
    __syncthreads();

    int ml = tid >> 3, d4 = tid & 7;
    float4 mv = memS[tid];
#pragma unroll
    for (int bi = 0; bi < 8; bi++) {
        float w = wS[bi][ml];
        float4 e = eS[bi][d4];
        float4 a = aS[bi][d4];
        float4 r;
        r.x = mv.x * (1.f - w * e.x) + w * a.x;
        r.y = mv.y * (1.f - w * e.y) + w * a.y;
        r.z = mv.z * (1.f - w * e.z) + w * a.z;
        r.w = mv.w * (1.f - w * e.w) + w * a.w;
        ((float4*)outw)[((size_t)(b0 + bi) * MSZ + m0 + ml) * 8 + d4] = r;
    }
}

// ---------------- launch ----------------
extern "C" void kernel_launch(void* const* d_in, const int* in_sizes, int n_in,
                              void* d_out, int out_size) {
    const float* x       = (const float*)d_in[0];
    const float* memory  = (const float*)d_in[1];
    // d_in[2] = W_rattn (dead: h=0), d_in[5] = W_hh (dead: h=0)
    const float* b_rattn = (const float*)d_in[3];
    const float* W_ih    = (const float*)d_in[4];
    const float* b_ih    = (const float*)d_in[6];
    const float* b_hh    = (const float*)d_in[7];
    const float* W_wattn = (const float*)d_in[8];
    const float* b_wattn = (const float*)d_in[9];
    const float* W_er    = (const float*)d_in[10];
    const float* b_er    = (const float*)d_in[11];
    const float* W_ad    = (const float*)d_in[12];
    const float* b_ad    = (const float*)d_in[13];
    const float* W_out   = (const float*)d_in[14];
    const float* b_out   = (const float*)d_in[15];

    float* out = (float*)d_out;            // [2048, 256]
    float* outw = out + BSZ * OUTSZ;       // [2048, 1024, 32]

    float *p_logits, *p_h, *p_outr;
    cudaGetSymbolAddress((void**)&p_logits, g_logits);
    cudaGetSymbolAddress((void**)&p_h, g_h);
    cudaGetSymbolAddress((void**)&p_outr, g_outr);

    k_read<<<1, 256>>>(b_rattn, memory);
    k_prep<<<5, 256>>>(W_ih, b_ih, b_hh, W_out, b_out);

    // h = LSTM(x @ W_ih[i,g,o]^T + g0) fused; f-gate skipped (c=0)
    k_gates<<<dim3(4, 32), 256>>>(x, W_ih, p_h);

    // wattn logits = h @ W_wattn^T + b_wattn  (tf32)
    gemm_tf32<128, 128><<<dim3(8, 16), 256>>>(p_h, W_wattn, CSZ, b_wattn, p_logits, MSZ);
    // output = h @ W_out[:, :256]^T + outr  (tf32; rvec part folded into outr)
    gemm_tf32<64, 64><<<dim3(4, 32), 256>>>(p_h, W_out, CSZ + DSZ, p_outr, out, OUTSZ);

    k_erad<<<BSZ, 64>>>(W_er, b_er, W_ad, b_ad);
    k_softmax<<<BSZ, 256>>>();
    k_write<<<dim3(MSZ / 32, BSZ / 8), 256>>>(memory, outw);
}

// round 13
// speedup vs baseline: 1.9341x; 1.1794x over previous
#include <cuda_runtime.h>
#include <math.h>

#define BSZ 2048
#define INSZ 256
#define CSZ 256
#define MSZ 1024
#define DSZ 32
#define OUTSZ 256

// ---------------- scratch (static device globals; no allocation) ----------------
__device__ float g_logits[BSZ * MSZ];      // 8 MB wattn logits (raw; softmax fused into write)
__device__ float g_h[BSZ * CSZ];           // 2 MB
__device__ float g_e[BSZ * DSZ];
__device__ float g_a[BSZ * DSZ];
__device__ float g_wmax[BSZ];
__device__ float g_winv[BSZ];
__device__ float g_rvec[DSZ];
__device__ float g_g0[4 * CSZ];
__device__ float g_outr[OUTSZ];

// ---------------- tf32 helpers ----------------
__device__ __forceinline__ unsigned f2tf32(float x) {
    unsigned r;
    asm("cvt.rna.tf32.f32 %0, %1;" : "=r"(r) : "f"(x));
    return r;
}

__device__ __forceinline__ void mma8(float* d, const unsigned* a, const unsigned* b) {
    asm volatile(
        "mma.sync.aligned.m16n8k8.row.col.f32.tf32.tf32.f32 "
        "{%0,%1,%2,%3}, {%4,%5,%6,%7}, {%8,%9}, {%0,%1,%2,%3};"
        : "+f"(d[0]), "+f"(d[1]), "+f"(d[2]), "+f"(d[3])
        : "r"(a[0]), "r"(a[1]), "r"(a[2]), "r"(a[3]), "r"(b[0]), "r"(b[1]));
}

__device__ __forceinline__ float sigf(float x) { return 1.f / (1.f + expf(-x)); }

// ---------------- kernel 1: read head (batch-independent since h=0) ----------------
__global__ __launch_bounds__(256) void k_read(const float* __restrict__ b_rattn,
                                              const float* __restrict__ memory) {
    __shared__ float p[MSZ];
    __shared__ float red[256];
    int tid = threadIdx.x;
    float v[4];
    float lm = -1e30f;
#pragma unroll
    for (int i = 0; i < 4; i++) {
        v[i] = b_rattn[tid + i * 256];
        lm = fmaxf(lm, v[i]);
    }
    red[tid] = lm;
    __syncthreads();
    for (int s = 128; s > 0; s >>= 1) {
        if (tid < s) red[tid] = fmaxf(red[tid], red[tid + s]);
        __syncthreads();
    }
    float mx = red[0];
    __syncthreads();
    float ls = 0.f;
#pragma unroll
    for (int i = 0; i < 4; i++) {
        float e = expf(v[i] - mx);
        p[tid + i * 256] = e;
        ls += e;
    }
    red[tid] = ls;
    __syncthreads();
    for (int s = 128; s > 0; s >>= 1) {
        if (tid < s) red[tid] += red[tid + s];
        __syncthreads();
    }
    float inv = 1.f / red[0];
    __syncthreads();
    int d = tid & 31, ch = tid >> 5;
    float s = 0.f;
    int m0 = ch * 128;
    for (int m = m0; m < m0 + 128; m++) s += p[m] * memory[m * DSZ + d];
    red[tid] = s * inv;
    __syncthreads();
    if (tid < 32) {
        float t = 0.f;
#pragma unroll
        for (int c = 0; c < 8; c++) t += red[c * 32 + tid];
        g_rvec[tid] = t;
    }
}

// ---------------- kernel 2: fold rvec into gate bias g0 and output bias outr ----------------
__global__ __launch_bounds__(256) void k_prep(const float* __restrict__ W_ih,
                                              const float* __restrict__ b_ih,
                                              const float* __restrict__ b_hh,
                                              const float* __restrict__ W_out,
                                              const float* __restrict__ b_out) {
    __shared__ float rv[DSZ];
    if (threadIdx.x < DSZ) rv[threadIdx.x] = g_rvec[threadIdx.x];
    __syncthreads();
    int idx = blockIdx.x * 256 + threadIdx.x;
    if (idx < 4 * CSZ) {
        const float* w = W_ih + (size_t)idx * (INSZ + DSZ) + INSZ;
        float s = b_ih[idx] + b_hh[idx];
#pragma unroll
        for (int d = 0; d < DSZ; d++) s += w[d] * rv[d];
        g_g0[idx] = s;
    } else if (idx < 4 * CSZ + OUTSZ) {
        int o = idx - 4 * CSZ;
        const float* w = W_out + (size_t)o * (CSZ + DSZ) + CSZ;
        float s = b_out[o];
#pragma unroll
        for (int d = 0; d < DSZ; d++) s += w[d] * rv[d];
        g_outr[o] = s;
    }
}

// ---------------- kernel 3: fused gates GEMM (tf32) + LSTM epilogue -> h ----------------
__global__ __launch_bounds__(256, 1) void k_gates(const float* __restrict__ x,
                                                  const float* __restrict__ W_ih,
                                                  float* __restrict__ hout) {
    __shared__ unsigned As[64][36];
    __shared__ unsigned Ws[3][64][36];
    const int tid = threadIdx.x;
    const int wid = tid >> 5, lane = tid & 31;
    const int gid = lane >> 2, tig = lane & 3;
    const int warp_m = wid & 1, warp_n = wid >> 1;
    const int bm = blockIdx.y, jn = blockIdx.x;
    const int lrow = tid >> 3, lk4 = (tid & 7) << 2;
    const int gate_off[3] = {0, 2 * CSZ, 3 * CSZ};

    float acc[3][2][2][4];
#pragma unroll
    for (int g = 0; g < 3; g++)
#pragma unroll
        for (int mt = 0; mt < 2; mt++)
#pragma unroll
            for (int nt = 0; nt < 2; nt++)
#pragma unroll
                for (int e = 0; e < 4; e++) acc[g][mt][nt][e] = 0.f;

    const float* Ap = x + (size_t)(bm * 64) * INSZ;

    for (int k0 = 0; k0 < 256; k0 += 32) {
#pragma unroll
        for (int r = 0; r < 2; r++) {
            int row = lrow + 32 * r;
            float4 v = *(const float4*)(Ap + (size_t)row * INSZ + k0 + lk4);
            *(uint4*)&As[row][lk4] = make_uint4(f2tf32(v.x), f2tf32(v.y), f2tf32(v.z), f2tf32(v.w));
        }
#pragma unroll
        for (int g = 0; g < 3; g++)
#pragma unroll
            for (int r = 0; r < 2; r++) {
                int row = lrow + 32 * r;
                int wr = gate_off[g] + jn * 64 + row;
                float4 v = *(const float4*)(W_ih + (size_t)wr * (INSZ + DSZ) + k0 + lk4);
                *(uint4*)&Ws[g][row][lk4] = make_uint4(f2tf32(v.x), f2tf32(v.y), f2tf32(v.z), f2tf32(v.w));
            }
        __syncthreads();
#pragma unroll
        for (int kk = 0; kk < 4; kk++) {
            int kb = kk * 8;
            unsigned af[2][4];
#pragma unroll
            for (int mt = 0; mt < 2; mt++) {
                int r0 = warp_m * 32 + mt * 16 + gid;
                af[mt][0] = As[r0][kb + tig];
                af[mt][1] = As[r0 + 8][kb + tig];
                af[mt][2] = As[r0][kb + tig + 4];
                af[mt][3] = As[r0 + 8][kb + tig + 4];
            }
#pragma unroll
            for (int g = 0; g < 3; g++) {
                unsigned bf[2][2];
#pragma unroll
                for (int nt = 0; nt < 2; nt++) {
                    int n0 = warp_n * 16 + nt * 8 + gid;
                    bf[nt][0] = Ws[g][n0][kb + tig];
                    bf[nt][1] = Ws[g][n0][kb + tig + 4];
                }
#pragma unroll
                for (int mt = 0; mt < 2; mt++)
#pragma unroll
                    for (int nt = 0; nt < 2; nt++) mma8(acc[g][mt][nt], af[mt], bf[nt]);
            }
        }
        __syncthreads();
    }

#pragma unroll
    for (int mt = 0; mt < 2; mt++)
#pragma unroll
        for (int nt = 0; nt < 2; nt++) {
            int row = bm * 64 + warp_m * 32 + mt * 16 + gid;
            int col = jn * 64 + warp_n * 16 + nt * 8 + 2 * tig;
            float bi0 = g_g0[col], bi1 = g_g0[col + 1];
            float bg0 = g_g0[2 * CSZ + col], bg1 = g_g0[2 * CSZ + col + 1];
            float bo0 = g_g0[3 * CSZ + col], bo1 = g_g0[3 * CSZ + col + 1];
            float i0 = acc[0][mt][nt][0] + bi0, i1 = acc[0][mt][nt][1] + bi1;
            float i2 = acc[0][mt][nt][2] + bi0, i3 = acc[0][mt][nt][3] + bi1;
            float gg0 = acc[1][mt][nt][0] + bg0, gg1 = acc[1][mt][nt][1] + bg1;
            float gg2 = acc[1][mt][nt][2] + bg0, gg3 = acc[1][mt][nt][3] + bg1;
            float o0 = acc[2][mt][nt][0] + bo0, o1 = acc[2][mt][nt][1] + bo1;
            float o2 = acc[2][mt][nt][2] + bo0, o3 = acc[2][mt][nt][3] + bo1;
            hout[(size_t)row * CSZ + col]           = sigf(o0) * tanhf(sigf(i0) * tanhf(gg0));
            hout[(size_t)row * CSZ + col + 1]       = sigf(o1) * tanhf(sigf(i1) * tanhf(gg1));
            hout[(size_t)(row + 8) * CSZ + col]     = sigf(o2) * tanhf(sigf(i2) * tanhf(gg2));
            hout[(size_t)(row + 8) * CSZ + col + 1] = sigf(o3) * tanhf(sigf(i3) * tanhf(gg3));
        }
}

// ---------------- generic tf32 GEMM: C[m,n] = sum_k A[m,k]*W[n*ldw+k] + bias[n] ----------------
template <int BM, int BN>
__global__ __launch_bounds__(256, 1) void gemm_tf32(const float* __restrict__ A,
                                                    const float* __restrict__ W, int ldw,
                                                    const float* __restrict__ bias,
                                                    float* __restrict__ C, int N) {
    constexpr int MT = BM / 32;
    constexpr int NT = BN / 32;
    __shared__ unsigned As[BM][36];
    __shared__ unsigned Ws[BN][36];
    const int tid = threadIdx.x;
    const int wid = tid >> 5, lane = tid & 31;
    const int gid = lane >> 2, tig = lane & 3;
    const int warp_m = wid & 1, warp_n = wid >> 1;
    const int bm = blockIdx.y, bn = blockIdx.x;
    const int lrow = tid >> 3, lk4 = (tid & 7) << 2;

    float acc[MT][NT][4];
#pragma unroll
    for (int mt = 0; mt < MT; mt++)
#pragma unroll
        for (int nt = 0; nt < NT; nt++)
#pragma unroll
            for (int e = 0; e < 4; e++) acc[mt][nt][e] = 0.f;

    const float* Ap = A + (size_t)(bm * BM) * 256;
    const float* Wp = W + (size_t)(bn * BN) * ldw;

    for (int k0 = 0; k0 < 256; k0 += 32) {
#pragma unroll
        for (int r = 0; r < BM / 32; r++) {
            int row = lrow + 32 * r;
            float4 v = *(const float4*)(Ap + (size_t)row * 256 + k0 + lk4);
            *(uint4*)&As[row][lk4] = make_uint4(f2tf32(v.x), f2tf32(v.y), f2tf32(v.z), f2tf32(v.w));
        }
#pragma unroll
        for (int r = 0; r < BN / 32; r++) {
            int row = lrow + 32 * r;
            float4 v = *(const float4*)(Wp + (size_t)row * ldw + k0 + lk4);
            *(uint4*)&Ws[row][lk4] = make_uint4(f2tf32(v.x), f2tf32(v.y), f2tf32(v.z), f2tf32(v.w));
        }
        __syncthreads();
#pragma unroll
        for (int kk = 0; kk < 4; kk++) {
            int kb = kk * 8;
            unsigned af[MT][4];
#pragma unroll
            for (int mt = 0; mt < MT; mt++) {
                int r0 = warp_m * (BM / 2) + mt * 16 + gid;
                af[mt][0] = As[r0][kb + tig];
                af[mt][1] = As[r0 + 8][kb + tig];
                af[mt][2] = As[r0][kb + tig + 4];
                af[mt][3] = As[r0 + 8][kb + tig + 4];
            }
            unsigned bf[NT][2];
#pragma unroll
            for (int nt = 0; nt < NT; nt++) {
                int n0 = warp_n * (BN / 4) + nt * 8 + gid;
                bf[nt][0] = Ws[n0][kb + tig];
                bf[nt][1] = Ws[n0][kb + tig + 4];
            }
#pragma unroll
            for (int mt = 0; mt < MT; mt++)
#pragma unroll
                for (int nt = 0; nt < NT; nt++) mma8(acc[mt][nt], af[mt], bf[nt]);
        }
        __syncthreads();
    }

#pragma unroll
    for (int mt = 0; mt < MT; mt++)
#pragma unroll
        for (int nt = 0; nt < NT; nt++) {
            int row = bm * BM + warp_m * (BM / 2) + mt * 16 + gid;
            int col = bn * BN + warp_n * (BN / 4) + nt * 8 + 2 * tig;
            float b0 = bias[col], b1 = bias[col + 1];
            C[(size_t)row * N + col]           = acc[mt][nt][0] + b0;
            C[(size_t)row * N + col + 1]       = acc[mt][nt][1] + b1;
            C[(size_t)(row + 8) * N + col]     = acc[mt][nt][2] + b0;
            C[(size_t)(row + 8) * N + col + 1] = acc[mt][nt][3] + b1;
        }
}

// ---------------- kernel 5: erase/add via tf32 mma: [2048,64] = h @ [W_er;W_ad]^T ----------------
// BM=64 rows/block, BN=64 (cols 0-31 -> sigmoid -> g_e, 32-63 -> tanh -> g_a). 32 CTAs.
__global__ __launch_bounds__(256, 1) void k_erad_mma(const float* __restrict__ W_er,
                                                     const float* __restrict__ b_er,
                                                     const float* __restrict__ W_ad,
                                                     const float* __restrict__ b_ad) {
    __shared__ unsigned As[64][36];
    __shared__ unsigned Ws[64][36];
    const int tid = threadIdx.x;
    const int wid = tid >> 5, lane = tid & 31;
    const int gid = lane >> 2, tig = lane & 3;
    const int warp_m = wid & 1, warp_n = wid >> 1;
    const int bm = blockIdx.x;
    const int lrow = tid >> 3, lk4 = (tid & 7) << 2;

    float acc[2][2][4];
#pragma unroll
    for (int mt = 0; mt < 2; mt++)
#pragma unroll
        for (int nt = 0; nt < 2; nt++)
#pragma unroll
            for (int e = 0; e < 4; e++) acc[mt][nt][e] = 0.f;

    const float* Ap = g_h + (size_t)(bm * 64) * CSZ;

    for (int k0 = 0; k0 < 256; k0 += 32) {
#pragma unroll
        for (int r = 0; r < 2; r++) {
            int row = lrow + 32 * r;
            float4 v = *(const float4*)(Ap + (size_t)row * CSZ + k0 + lk4);
            *(uint4*)&As[row][lk4] = make_uint4(f2tf32(v.x), f2tf32(v.y), f2tf32(v.z), f2tf32(v.w));
        }
        {
            float4 v = *(const float4*)(W_er + (size_t)lrow * CSZ + k0 + lk4);
            *(uint4*)&Ws[lrow][lk4] = make_uint4(f2tf32(v.x), f2tf32(v.y), f2tf32(v.z), f2tf32(v.w));
            float4 u = *(const float4*)(W_ad + (size_t)lrow * CSZ + k0 + lk4);
            *(uint4*)&Ws[lrow + 32][lk4] = make_uint4(f2tf32(u.x), f2tf32(u.y), f2tf32(u.z), f2tf32(u.w));
        }
        __syncthreads();
#pragma unroll
        for (int kk = 0; kk < 4; kk++) {
            int kb = kk * 8;
            unsigned af[2][4];
#pragma unroll
            for (int mt = 0; mt < 2; mt++) {
                int r0 = warp_m * 32 + mt * 16 + gid;
                af[mt][0] = As[r0][kb + tig];
                af[mt][1] = As[r0 + 8][kb + tig];
                af[mt][2] = As[r0][kb + tig + 4];
                af[mt][3] = As[r0 + 8][kb + tig + 4];
            }
            unsigned bf[2][2];
#pragma unroll
            for (int nt = 0; nt < 2; nt++) {
                int n0 = warp_n * 16 + nt * 8 + gid;
                bf[nt][0] = Ws[n0][kb + tig];
                bf[nt][1] = Ws[n0][kb + tig + 4];
            }
#pragma unroll
            for (int mt = 0; mt < 2; mt++)
#pragma unroll
                for (int nt = 0; nt < 2; nt++) mma8(acc[mt][nt], af[mt], bf[nt]);
        }
        __syncthreads();
    }

#pragma unroll
    for (int mt = 0; mt < 2; mt++)
#pragma unroll
        for (int nt = 0; nt < 2; nt++) {
            int row = bm * 64 + warp_m * 32 + mt * 16 + gid;
            int col = warp_n * 16 + nt * 8 + 2 * tig;
#pragma unroll
            for (int e = 0; e < 4; e++) {
                int rr = row + (e >> 1) * 8;
                int cc = col + (e & 1);
                float v = acc[mt][nt][e];
                if (cc < DSZ) {
                    g_e[(size_t)rr * DSZ + cc] = sigf(v + b_er[cc]);
                } else {
                    g_a[(size_t)rr * DSZ + (cc - DSZ)] = tanhf(v + b_ad[cc - DSZ]);
                }
            }
        }
}

// ---------------- kernel 6: per-row softmax stats (max + 1/sum) over wattn logits ----------------
__global__ __launch_bounds__(256) void k_rowstat() {
    const float4* row = (const float4*)(g_logits + (size_t)blockIdx.x * MSZ);
    int tid = threadIdx.x;
    __shared__ float red[256];
    float4 v = row[tid];
    float lm = fmaxf(fmaxf(v.x, v.y), fmaxf(v.z, v.w));
    red[tid] = lm;
    __syncthreads();
    for (int s = 128; s > 0; s >>= 1) {
        if (tid < s) red[tid] = fmaxf(red[tid], red[tid + s]);
        __syncthreads();
    }
    float mx = red[0];
    __syncthreads();
    float ls = expf(v.x - mx) + expf(v.y - mx) + expf(v.z - mx) + expf(v.w - mx);
    red[tid] = ls;
    __syncthreads();
    for (int s = 128; s > 0; s >>= 1) {
        if (tid < s) red[tid] += red[tid + s];
        __syncthreads();
    }
    if (tid == 0) {
        g_wmax[blockIdx.x] = mx;
        g_winv[blockIdx.x] = 1.f / red[0];
    }
}

// ---------------- kernel 7: write_data (HBM-store-bound; softmax applied inline) ----------------
__global__ __launch_bounds__(256) void k_write(const float* __restrict__ memory,
                                               float* __restrict__ outw) {
    __shared__ float4 memS[256];
    __shared__ float wS[8][32];
    __shared__ float4 eS[8][8];
    __shared__ float4 aS[8][8];
    int tid = threadIdx.x;
    int m0 = blockIdx.x * 32;
    int b0 = blockIdx.y * 8;

    memS[tid] = ((const float4*)memory)[(size_t)(m0 + (tid >> 3)) * 8 + (tid & 7)];
    {
        int bi = tid >> 5, ml = tid & 31;
        int b = b0 + bi;
        float logit = g_logits[(size_t)b * MSZ + m0 + ml];
        wS[bi][ml] = expf(logit - g_wmax[b]) * g_winv[b];
    }
    if (tid < 64) {
        eS[tid >> 3][tid & 7] = ((const float4*)g_e)[(size_t)(b0 + (tid >> 3)) * 8 + (tid & 7)];
    } else if (tid < 128) {
        int t = tid - 64;
        aS[t >> 3][t & 7] = ((const float4*)g_a)[(size_t)(b0 + (t >> 3)) * 8 + (t & 7)];
    }
    __syncthreads();

    int ml = tid >> 3, d4 = tid & 7;
    float4 mv = memS[tid];
#pragma unroll
    for (int bi = 0; bi < 8; bi++) {
        float w = wS[bi][ml];
        float4 e = eS[bi][d4];
        float4 a = aS[bi][d4];
        float4 r;
        r.x = mv.x * (1.f - w * e.x) + w * a.x;
        r.y = mv.y * (1.f - w * e.y) + w * a.y;
        r.z = mv.z * (1.f - w * e.z) + w * a.z;
        r.w = mv.w * (1.f - w * e.w) + w * a.w;
        ((float4*)outw)[((size_t)(b0 + bi) * MSZ + m0 + ml) * 8 + d4] = r;
    }
}

// ---------------- launch ----------------
extern "C" void kernel_launch(void* const* d_in, const int* in_sizes, int n_in,
                              void* d_out, int out_size) {
    const float* x       = (const float*)d_in[0];
    const float* memory  = (const float*)d_in[1];
    // d_in[2] = W_rattn (dead: h=0), d_in[5] = W_hh (dead: h=0)
    const float* b_rattn = (const float*)d_in[3];
    const float* W_ih    = (const float*)d_in[4];
    const float* b_ih    = (const float*)d_in[6];
    const float* b_hh    = (const float*)d_in[7];
    const float* W_wattn = (const float*)d_in[8];
    const float* b_wattn = (const float*)d_in[9];
    const float* W_er    = (const float*)d_in[10];
    const float* b_er    = (const float*)d_in[11];
    const float* W_ad    = (const float*)d_in[12];
    const float* b_ad    = (const float*)d_in[13];
    const float* W_out   = (const float*)d_in[14];
    const float* b_out   = (const float*)d_in[15];

    float* out = (float*)d_out;            // [2048, 256]
    float* outw = out + BSZ * OUTSZ;       // [2048, 1024, 32]

    float *p_logits, *p_h, *p_outr;
    cudaGetSymbolAddress((void**)&p_logits, g_logits);
    cudaGetSymbolAddress((void**)&p_h, g_h);
    cudaGetSymbolAddress((void**)&p_outr, g_outr);

    k_read<<<1, 256>>>(b_rattn, memory);
    k_prep<<<5, 256>>>(W_ih, b_ih, b_hh, W_out, b_out);

    // h = LSTM(x @ W_ih[i,g,o]^T + g0) fused; f-gate skipped (c=0)
    k_gates<<<dim3(4, 32), 256>>>(x, W_ih, p_h);

    // wattn logits = h @ W_wattn^T + b_wattn  (tf32, 64x64 tiles for occupancy)
    gemm_tf32<64, 64><<<dim3(16, 32), 256>>>(p_h, W_wattn, CSZ, b_wattn, p_logits, MSZ);
    // output = h @ W_out[:, :256]^T + outr  (tf32; rvec part folded into outr)
    gemm_tf32<64, 64><<<dim3(4, 32), 256>>>(p_h, W_out, CSZ + DSZ, p_outr, out, OUTSZ);

    // e/a via tf32 mma (replaces LDG-bound k_erad)
    k_erad_mma<<<32, 256>>>(W_er, b_er, W_ad, b_ad);

    k_rowstat<<<BSZ, 256>>>();
    k_write<<<dim3(MSZ / 32, BSZ / 8), 256>>>(memory, outw);
}

// round 16
// speedup vs baseline: 1.9378x; 1.0019x over previous
#include <cuda_runtime.h>
#include <math.h>

#define BSZ 2048
#define INSZ 256
#define CSZ 256
#define MSZ 1024
#define DSZ 32
#define OUTSZ 256

// ---------------- scratch (static device globals; no allocation) ----------------
__device__ float g_logits[BSZ * MSZ];      // 8 MB wattn logits (raw; softmax fused into write)
__device__ float g_h[BSZ * CSZ];           // 2 MB
__device__ float g_e[BSZ * DSZ];
__device__ float g_a[BSZ * DSZ];
__device__ float g_wmax[BSZ];
__device__ float g_winv[BSZ];
__device__ float g_rvec[DSZ];
__device__ float g_g0[4 * CSZ];
__device__ float g_outr[OUTSZ];

// ---------------- tf32 helpers ----------------
__device__ __forceinline__ unsigned f2tf32(float x) {
    unsigned r;
    asm("cvt.rna.tf32.f32 %0, %1;" : "=r"(r) : "f"(x));
    return r;
}

__device__ __forceinline__ void mma8(float* d, const unsigned* a, const unsigned* b) {
    asm volatile(
        "mma.sync.aligned.m16n8k8.row.col.f32.tf32.tf32.f32 "
        "{%0,%1,%2,%3}, {%4,%5,%6,%7}, {%8,%9}, {%0,%1,%2,%3};"
        : "+f"(d[0]), "+f"(d[1]), "+f"(d[2]), "+f"(d[3])
        : "r"(a[0]), "r"(a[1]), "r"(a[2]), "r"(a[3]), "r"(b[0]), "r"(b[1]));
}

__device__ __forceinline__ uint4 cvt4(float4 v) {
    return make_uint4(f2tf32(v.x), f2tf32(v.y), f2tf32(v.z), f2tf32(v.w));
}

__device__ __forceinline__ float sigf(float x) { return 1.f / (1.f + expf(-x)); }

// ---------------- kernel 1: read head (batch-independent since h=0) ----------------
__global__ __launch_bounds__(256) void k_read(const float* __restrict__ b_rattn,
                                              const float* __restrict__ memory) {
    __shared__ float p[MSZ];
    __shared__ float red[256];
    int tid = threadIdx.x;
    float v[4];
    float lm = -1e30f;
#pragma unroll
    for (int i = 0; i < 4; i++) {
        v[i] = b_rattn[tid + i * 256];
        lm = fmaxf(lm, v[i]);
    }
    red[tid] = lm;
    __syncthreads();
    for (int s = 128; s > 0; s >>= 1) {
        if (tid < s) red[tid] = fmaxf(red[tid], red[tid + s]);
        __syncthreads();
    }
    float mx = red[0];
    __syncthreads();
    float ls = 0.f;
#pragma unroll
    for (int i = 0; i < 4; i++) {
        float e = expf(v[i] - mx);
        p[tid + i * 256] = e;
        ls += e;
    }
    red[tid] = ls;
    __syncthreads();
    for (int s = 128; s > 0; s >>= 1) {
        if (tid < s) red[tid] += red[tid + s];
        __syncthreads();
    }
    float inv = 1.f / red[0];
    __syncthreads();
    int d = tid & 31, ch = tid >> 5;
    float s = 0.f;
    int m0 = ch * 128;
    for (int m = m0; m < m0 + 128; m++) s += p[m] * memory[m * DSZ + d];
    red[tid] = s * inv;
    __syncthreads();
    if (tid < 32) {
        float t = 0.f;
#pragma unroll
        for (int c = 0; c < 8; c++) t += red[c * 32 + tid];
        g_rvec[tid] = t;
    }
}

// ---------------- kernel 2: fold rvec into gate bias g0 and output bias outr ----------------
__global__ __launch_bounds__(256) void k_prep(const float* __restrict__ W_ih,
                                              const float* __restrict__ b_ih,
                                              const float* __restrict__ b_hh,
                                              const float* __restrict__ W_out,
                                              const float* __restrict__ b_out) {
    __shared__ float rv[DSZ];
    if (threadIdx.x < DSZ) rv[threadIdx.x] = g_rvec[threadIdx.x];
    __syncthreads();
    int idx = blockIdx.x * 256 + threadIdx.x;
    if (idx < 4 * CSZ) {
        const float* w = W_ih + (size_t)idx * (INSZ + DSZ) + INSZ;
        float s = b_ih[idx] + b_hh[idx];
#pragma unroll
        for (int d = 0; d < DSZ; d++) s += w[d] * rv[d];
        g_g0[idx] = s;
    } else if (idx < 4 * CSZ + OUTSZ) {
        int o = idx - 4 * CSZ;
        const float* w = W_out + (size_t)o * (CSZ + DSZ) + CSZ;
        float s = b_out[o];
#pragma unroll
        for (int d = 0; d < DSZ; d++) s += w[d] * rv[d];
        g_outr[o] = s;
    }
}

// ---------------- kernel 3: fused gates GEMM (tf32, double-buffered BK=16) + LSTM epilogue ----------------
__global__ __launch_bounds__(256, 1) void k_gates(const float* __restrict__ x,
                                                  const float* __restrict__ W_ih,
                                                  float* __restrict__ hout) {
    __shared__ unsigned As[2][64][20];
    __shared__ unsigned Ws[3][2][64][20];
    const int tid = threadIdx.x;
    const int wid = tid >> 5, lane = tid & 31;
    const int gid = lane >> 2, tig = lane & 3;
    const int warp_m = wid & 1, warp_n = wid >> 1;
    const int bm = blockIdx.y, jn = blockIdx.x;
    const int lrow = tid >> 2, lk4 = (tid & 3) << 2;   // 64 rows x 16 cols per pass
    const int gate_off[3] = {0, 2 * CSZ, 3 * CSZ};

    const float* Ap = x + (size_t)(bm * 64) * INSZ + (size_t)lrow * INSZ + lk4;
    const float* Wp[3];
#pragma unroll
    for (int g = 0; g < 3; g++)
        Wp[g] = W_ih + (size_t)(gate_off[g] + jn * 64 + lrow) * (INSZ + DSZ) + lk4;

    float4 ra = *(const float4*)(Ap);
    float4 rw[3];
#pragma unroll
    for (int g = 0; g < 3; g++) rw[g] = *(const float4*)(Wp[g]);
    *(uint4*)&As[0][lrow][lk4] = cvt4(ra);
#pragma unroll
    for (int g = 0; g < 3; g++) *(uint4*)&Ws[g][0][lrow][lk4] = cvt4(rw[g]);
    __syncthreads();

    float acc[3][2][2][4];
#pragma unroll
    for (int g = 0; g < 3; g++)
#pragma unroll
        for (int mt = 0; mt < 2; mt++)
#pragma unroll
            for (int nt = 0; nt < 2; nt++)
#pragma unroll
                for (int e = 0; e < 4; e++) acc[g][mt][nt][e] = 0.f;

    for (int it = 0; it < 16; it++) {
        if (it < 15) {
            int k0 = (it + 1) * 16;
            ra = *(const float4*)(Ap + k0);
#pragma unroll
            for (int g = 0; g < 3; g++) rw[g] = *(const float4*)(Wp[g] + k0);
        }
        const int cur = it & 1;
#pragma unroll
        for (int kk = 0; kk < 2; kk++) {
            int kb = kk * 8;
            unsigned af[2][4];
#pragma unroll
            for (int mt = 0; mt < 2; mt++) {
                int r0 = warp_m * 32 + mt * 16 + gid;
                af[mt][0] = As[cur][r0][kb + tig];
                af[mt][1] = As[cur][r0 + 8][kb + tig];
                af[mt][2] = As[cur][r0][kb + tig + 4];
                af[mt][3] = As[cur][r0 + 8][kb + tig + 4];
            }
#pragma unroll
            for (int g = 0; g < 3; g++) {
                unsigned bf[2][2];
#pragma unroll
                for (int nt = 0; nt < 2; nt++) {
                    int n0 = warp_n * 16 + nt * 8 + gid;
                    bf[nt][0] = Ws[g][cur][n0][kb + tig];
                    bf[nt][1] = Ws[g][cur][n0][kb + tig + 4];
                }
#pragma unroll
                for (int mt = 0; mt < 2; mt++)
#pragma unroll
                    for (int nt = 0; nt < 2; nt++) mma8(acc[g][mt][nt], af[mt], bf[nt]);
            }
        }
        if (it < 15) {
            const int nxt = cur ^ 1;
            *(uint4*)&As[nxt][lrow][lk4] = cvt4(ra);
#pragma unroll
            for (int g = 0; g < 3; g++) *(uint4*)&Ws[g][nxt][lrow][lk4] = cvt4(rw[g]);
            __syncthreads();
        }
    }

    // LSTM epilogue: h = sigmoid(o) * tanh(sigmoid(i) * tanh(g))
#pragma unroll
    for (int mt = 0; mt < 2; mt++)
#pragma unroll
        for (int nt = 0; nt < 2; nt++) {
            int row = bm * 64 + warp_m * 32 + mt * 16 + gid;
            int col = jn * 64 + warp_n * 16 + nt * 8 + 2 * tig;
            float bi0 = g_g0[col], bi1 = g_g0[col + 1];
            float bg0 = g_g0[2 * CSZ + col], bg1 = g_g0[2 * CSZ + col + 1];
            float bo0 = g_g0[3 * CSZ + col], bo1 = g_g0[3 * CSZ + col + 1];
            float i0 = acc[0][mt][nt][0] + bi0, i1 = acc[0][mt][nt][1] + bi1;
            float i2 = acc[0][mt][nt][2] + bi0, i3 = acc[0][mt][nt][3] + bi1;
            float gg0 = acc[1][mt][nt][0] + bg0, gg1 = acc[1][mt][nt][1] + bg1;
            float gg2 = acc[1][mt][nt][2] + bg0, gg3 = acc[1][mt][nt][3] + bg1;
            float o0 = acc[2][mt][nt][0] + bo0, o1 = acc[2][mt][nt][1] + bo1;
            float o2 = acc[2][mt][nt][2] + bo0, o3 = acc[2][mt][nt][3] + bo1;
            hout[(size_t)row * CSZ + col]           = sigf(o0) * tanhf(sigf(i0) * tanhf(gg0));
            hout[(size_t)row * CSZ + col + 1]       = sigf(o1) * tanhf(sigf(i1) * tanhf(gg1));
            hout[(size_t)(row + 8) * CSZ + col]     = sigf(o2) * tanhf(sigf(i2) * tanhf(gg2));
            hout[(size_t)(row + 8) * CSZ + col + 1] = sigf(o3) * tanhf(sigf(i3) * tanhf(gg3));
        }
}

// ---------------- 64x64 tf32 GEMM, double-buffered (BK=32): C = A @ W^T + bias ----------------
__global__ __launch_bounds__(256, 1) void gemm64_db(const float* __restrict__ A,
                                                    const float* __restrict__ W, int ldw,
                                                    const float* __restrict__ bias,
                                                    float* __restrict__ C, int N) {
    __shared__ unsigned As[2][64][36];
    __shared__ unsigned Ws[2][64][36];
    const int tid = threadIdx.x;
    const int wid = tid >> 5, lane = tid & 31;
    const int gid = lane >> 2, tig = lane & 3;
    const int warp_m = wid & 1, warp_n = wid >> 1;
    const int bm = blockIdx.y, bn = blockIdx.x;
    const int lrow = tid >> 3, lk4 = (tid & 7) << 2;

    const float* Ap = A + (size_t)(bm * 64) * 256;
    const float* Wp = W + (size_t)(bn * 64) * ldw;

    float4 ra0 = *(const float4*)(Ap + (size_t)lrow * 256 + lk4);
    float4 ra1 = *(const float4*)(Ap + (size_t)(lrow + 32) * 256 + lk4);
    float4 rw0 = *(const float4*)(Wp + (size_t)lrow * ldw + lk4);
    float4 rw1 = *(const float4*)(Wp + (size_t)(lrow + 32) * ldw + lk4);
    *(uint4*)&As[0][lrow][lk4]      = cvt4(ra0);
    *(uint4*)&As[0][lrow + 32][lk4] = cvt4(ra1);
    *(uint4*)&Ws[0][lrow][lk4]      = cvt4(rw0);
    *(uint4*)&Ws[0][lrow + 32][lk4] = cvt4(rw1);
    __syncthreads();

    float acc[2][2][4];
#pragma unroll
    for (int mt = 0; mt < 2; mt++)
#pragma unroll
        for (int nt = 0; nt < 2; nt++)
#pragma unroll
            for (int e = 0; e < 4; e++) acc[mt][nt][e] = 0.f;

    for (int it = 0; it < 8; it++) {
        if (it < 7) {
            int k0 = (it + 1) * 32;
            ra0 = *(const float4*)(Ap + (size_t)lrow * 256 + k0 + lk4);
            ra1 = *(const float4*)(Ap + (size_t)(lrow + 32) * 256 + k0 + lk4);
            rw0 = *(const float4*)(Wp + (size_t)lrow * ldw + k0 + lk4);
            rw1 = *(const float4*)(Wp + (size_t)(lrow + 32) * ldw + k0 + lk4);
        }
        const int cur = it & 1;
#pragma unroll
        for (int kk = 0; kk < 4; kk++) {
            int kb = kk * 8;
            unsigned af[2][4];
#pragma unroll
            for (int mt = 0; mt < 2; mt++) {
                int r0 = warp_m * 32 + mt * 16 + gid;
                af[mt][0] = As[cur][r0][kb + tig];
                af[mt][1] = As[cur][r0 + 8][kb + tig];
                af[mt][2] = As[cur][r0][kb + tig + 4];
                af[mt][3] = As[cur][r0 + 8][kb + tig + 4];
            }
            unsigned bf[2][2];
#pragma unroll
            for (int nt = 0; nt < 2; nt++) {
                int n0 = warp_n * 16 + nt * 8 + gid;
                bf[nt][0] = Ws[cur][n0][kb + tig];
                bf[nt][1] = Ws[cur][n0][kb + tig + 4];
            }
#pragma unroll
            for (int mt = 0; mt < 2; mt++)
#pragma unroll
                for (int nt = 0; nt < 2; nt++) mma8(acc[mt][nt], af[mt], bf[nt]);
        }
        if (it < 7) {
            const int nxt = cur ^ 1;
            *(uint4*)&As[nxt][lrow][lk4]      = cvt4(ra0);
            *(uint4*)&As[nxt][lrow + 32][lk4] = cvt4(ra1);
            *(uint4*)&Ws[nxt][lrow][lk4]      = cvt4(rw0);
            *(uint4*)&Ws[nxt][lrow + 32][lk4] = cvt4(rw1);
            __syncthreads();
        }
    }

#pragma unroll
    for (int mt = 0; mt < 2; mt++)
#pragma unroll
        for (int nt = 0; nt < 2; nt++) {
            int row = bm * 64 + warp_m * 32 + mt * 16 + gid;
            int col = bn * 64 + warp_n * 16 + nt * 8 + 2 * tig;
            float b0 = bias[col], b1 = bias[col + 1];
            C[(size_t)row * N + col]           = acc[mt][nt][0] + b0;
            C[(size_t)row * N + col + 1]       = acc[mt][nt][1] + b1;
            C[(size_t)(row + 8) * N + col]     = acc[mt][nt][2] + b0;
            C[(size_t)(row + 8) * N + col + 1] = acc[mt][nt][3] + b1;
        }
}

// ---------------- kernel 5: erase/add via tf32 mma (double-buffered) ----------------
__global__ __launch_bounds__(256, 1) void k_erad_mma(const float* __restrict__ W_er,
                                                     const float* __restrict__ b_er,
                                                     const float* __restrict__ W_ad,
                                                     const float* __restrict__ b_ad) {
    __shared__ unsigned As[2][64][36];
    __shared__ unsigned Ws[2][64][36];
    const int tid = threadIdx.x;
    const int wid = tid >> 5, lane = tid & 31;
    const int gid = lane >> 2, tig = lane & 3;
    const int warp_m = wid & 1, warp_n = wid >> 1;
    const int bm = blockIdx.x;
    const int lrow = tid >> 3, lk4 = (tid & 7) << 2;

    const float* Ap = g_h + (size_t)(bm * 64) * CSZ;

    float4 ra0 = *(const float4*)(Ap + (size_t)lrow * CSZ + lk4);
    float4 ra1 = *(const float4*)(Ap + (size_t)(lrow + 32) * CSZ + lk4);
    float4 rwe = *(const float4*)(W_er + (size_t)lrow * CSZ + lk4);
    float4 rwa = *(const float4*)(W_ad + (size_t)lrow * CSZ + lk4);
    *(uint4*)&As[0][lrow][lk4]      = cvt4(ra0);
    *(uint4*)&As[0][lrow + 32][lk4] = cvt4(ra1);
    *(uint4*)&Ws[0][lrow][lk4]      = cvt4(rwe);
    *(uint4*)&Ws[0][lrow + 32][lk4] = cvt4(rwa);
    __syncthreads();

    float acc[2][2][4];
#pragma unroll
    for (int mt = 0; mt < 2; mt++)
#pragma unroll
        for (int nt = 0; nt < 2; nt++)
#pragma unroll
            for (int e = 0; e < 4; e++) acc[mt][nt][e] = 0.f;

    for (int it = 0; it < 8; it++) {
        if (it < 7) {
            int k0 = (it + 1) * 32;
            ra0 = *(const float4*)(Ap + (size_t)lrow * CSZ + k0 + lk4);
            ra1 = *(const float4*)(Ap + (size_t)(lrow + 32) * CSZ + k0 + lk4);
            rwe = *(const float4*)(W_er + (size_t)lrow * CSZ + k0 + lk4);
            rwa = *(const float4*)(W_ad + (size_t)lrow * CSZ + k0 + lk4);
        }
        const int cur = it & 1;
#pragma unroll
        for (int kk = 0; kk < 4; kk++) {
            int kb = kk * 8;
            unsigned af[2][4];
#pragma unroll
            for (int mt = 0; mt < 2; mt++) {
                int r0 = warp_m * 32 + mt * 16 + gid;
                af[mt][0] = As[cur][r0][kb + tig];
                af[mt][1] = As[cur][r0 + 8][kb + tig];
                af[mt][2] = As[cur][r0][kb + tig + 4];
                af[mt][3] = As[cur][r0 + 8][kb + tig + 4];
            }
            unsigned bf[2][2];
#pragma unroll
            for (int nt = 0; nt < 2; nt++) {
                int n0 = warp_n * 16 + nt * 8 + gid;
                bf[nt][0] = Ws[cur][n0][kb + tig];
                bf[nt][1] = Ws[cur][n0][kb + tig + 4];
            }
#pragma unroll
            for (int mt = 0; mt < 2; mt++)
#pragma unroll
                for (int nt = 0; nt < 2; nt++) mma8(acc[mt][nt], af[mt], bf[nt]);
        }
        if (it < 7) {
            const int nxt = cur ^ 1;
            *(uint4*)&As[nxt][lrow][lk4]      = cvt4(ra0);
            *(uint4*)&As[nxt][lrow + 32][lk4] = cvt4(ra1);
            *(uint4*)&Ws[nxt][lrow][lk4]      = cvt4(rwe);
            *(uint4*)&Ws[nxt][lrow + 32][lk4] = cvt4(rwa);
            __syncthreads();
        }
    }

#pragma unroll
    for (int mt = 0; mt < 2; mt++)
#pragma unroll
        for (int nt = 0; nt < 2; nt++) {
            int row = bm * 64 + warp_m * 32 + mt * 16 + gid;
            int col = warp_n * 16 + nt * 8 + 2 * tig;
#pragma unroll
            for (int e = 0; e < 4; e++) {
                int rr = row + (e >> 1) * 8;
                int cc = col + (e & 1);
                float v = acc[mt][nt][e];
                if (cc < DSZ) {
                    g_e[(size_t)rr * DSZ + cc] = sigf(v + b_er[cc]);
                } else {
                    g_a[(size_t)rr * DSZ + (cc - DSZ)] = tanhf(v + b_ad[cc - DSZ]);
                }
            }
        }
}

// ---------------- kernel 6: per-row softmax stats (max + 1/sum) over wattn logits ----------------
__global__ __launch_bounds__(256) void k_rowstat() {
    const float4* row = (const float4*)(g_logits + (size_t)blockIdx.x * MSZ);
    int tid = threadIdx.x;
    __shared__ float red[256];
    float4 v = row[tid];
    float lm = fmaxf(fmaxf(v.x, v.y), fmaxf(v.z, v.w));
    red[tid] = lm;
    __syncthreads();
    for (int s = 128; s > 0; s >>= 1) {
        if (tid < s) red[tid] = fmaxf(red[tid], red[tid + s]);
        __syncthreads();
    }
    float mx = red[0];
    __syncthreads();
    float ls = expf(v.x - mx) + expf(v.y - mx) + expf(v.z - mx) + expf(v.w - mx);
    red[tid] = ls;
    __syncthreads();
    for (int s = 128; s > 0; s >>= 1) {
        if (tid < s) red[tid] += red[tid + s];
        __syncthreads();
    }
    if (tid == 0) {
        g_wmax[blockIdx.x] = mx;
        g_winv[blockIdx.x] = 1.f / red[0];
    }
}

// ---------------- kernel 7: write_data (HBM-store-bound; softmax applied inline) ----------------
__global__ __launch_bounds__(256) void k_write(const float* __restrict__ memory,
                                               float* __restrict__ outw) {
    __shared__ float4 memS[256];
    __shared__ float wS[8][32];
    __shared__ float4 eS[8][8];
    __shared__ float4 aS[8][8];
    int tid = threadIdx.x;
    int m0 = blockIdx.x * 32;
    int b0 = blockIdx.y * 8;

    memS[tid] = ((const float4*)memory)[(size_t)(m0 + (tid >> 3)) * 8 + (tid & 7)];
    {
        int bi = tid >> 5, ml = tid & 31;
        int b = b0 + bi;
        float logit = g_logits[(size_t)b * MSZ + m0 + ml];
        wS[bi][ml] = expf(logit - g_wmax[b]) * g_winv[b];
    }
    if (tid < 64) {
        eS[tid >> 3][tid & 7] = ((const float4*)g_e)[(size_t)(b0 + (tid >> 3)) * 8 + (tid & 7)];
    } else if (tid < 128) {
        int t = tid - 64;
        aS[t >> 3][t & 7] = ((const float4*)g_a)[(size_t)(b0 + (t >> 3)) * 8 + (t & 7)];
    }
    __syncthreads();

    int ml = tid >> 3, d4 = tid & 7;
    float4 mv = memS[tid];
#pragma unroll
    for (int bi = 0; bi < 8; bi++) {
        float w = wS[bi][ml];
        float4 e = eS[bi][d4];
        float4 a = aS[bi][d4];
        float4 r;
        r.x = mv.x * (1.f - w * e.x) + w * a.x;
        r.y = mv.y * (1.f - w * e.y) + w * a.y;
        r.z = mv.z * (1.f - w * e.z) + w * a.z;
        r.w = mv.w * (1.f - w * e.w) + w * a.w;
        ((float4*)outw)[((size_t)(b0 + bi) * MSZ + m0 + ml) * 8 + d4] = r;
    }
}

// ---------------- launch ----------------
extern "C" void kernel_launch(void* const* d_in, const int* in_sizes, int n_in,
                              void* d_out, int out_size) {
    const float* x       = (const float*)d_in[0];
    const float* memory  = (const float*)d_in[1];
    // d_in[2] = W_rattn (dead: h=0), d_in[5] = W_hh (dead: h=0)
    const float* b_rattn = (const float*)d_in[3];
    const float* W_ih    = (const float*)d_in[4];
    const float* b_ih    = (const float*)d_in[6];
    const float* b_hh    = (const float*)d_in[7];
    const float* W_wattn = (const float*)d_in[8];
    const float* b_wattn = (const float*)d_in[9];
    const float* W_er    = (const float*)d_in[10];
    const float* b_er    = (const float*)d_in[11];
    const float* W_ad    = (const float*)d_in[12];
    const float* b_ad    = (const float*)d_in[13];
    const float* W_out   = (const float*)d_in[14];
    const float* b_out   = (const float*)d_in[15];

    float* out = (float*)d_out;            // [2048, 256]
    float* outw = out + BSZ * OUTSZ;       // [2048, 1024, 32]

    float *p_logits, *p_h, *p_outr;
    cudaGetSymbolAddress((void**)&p_logits, g_logits);
    cudaGetSymbolAddress((void**)&p_h, g_h);
    cudaGetSymbolAddress((void**)&p_outr, g_outr);

    k_read<<<1, 256>>>(b_rattn, memory);
    k_prep<<<5, 256>>>(W_ih, b_ih, b_hh, W_out, b_out);

    // h = LSTM(x @ W_ih[i,g,o]^T + g0) fused; f-gate skipped (c=0)
    k_gates<<<dim3(4, 32), 256>>>(x, W_ih, p_h);

    // wattn logits = h @ W_wattn^T + b_wattn  (tf32, pipelined)
    gemm64_db<<<dim3(16, 32), 256>>>(p_h, W_wattn, CSZ, b_wattn, p_logits, MSZ);
    // output = h @ W_out[:, :256]^T + outr  (tf32; rvec part folded into outr)
    gemm64_db<<<dim3(4, 32), 256>>>(p_h, W_out, CSZ + DSZ, p_outr, out, OUTSZ);

    // e/a via tf32 mma (pipelined)
    k_erad_mma<<<32, 256>>>(W_er, b_er, W_ad, b_ad);

    k_rowstat<<<BSZ, 256>>>();
    k_write<<<dim3(MSZ / 32, BSZ / 8), 256>>>(memory, outw);
}